// round 2
// baseline (speedup 1.0000x reference)
#include <cuda_runtime.h>
#include <stdint.h>

// Problem constants (fixed shapes per dataset)
#define Nn      8192
#define Cc      128
#define Ee      262144
#define NWORDS  ((Nn / 32) * Nn)   // 2,097,152 words = 8 MB bitmask

// -------- scratch (device globals: allocation-free) --------
__device__ uint32_t g_bitmask[NWORDS];   // 8 MB dedup bitmask
__device__ int      g_deg[Nn];
__device__ int      g_fill[Nn];
__device__ int      g_ptr[Nn + 1];
__device__ float    g_dinv[Nn];          // deg^-1/2
__device__ int      g_nnz;
__device__ int      g_elist[Ee];         // packed (s<<13)|d, dedup'd
__device__ int      g_csr[Ee];           // CSR column indices
__device__ float    g_bufA[Nn * Cc];
__device__ float    g_bufB[Nn * Cc];
__device__ double   g_pos, g_neg;
__device__ int      g_is64;              // 1 if index inputs are int64, 0 if int32

// index fetch that works for both int32 and int64 input storage
__device__ __forceinline__ int fetch_idx(const void* __restrict__ p, int i) {
    if (g_is64) return (int)((const long long*)p)[i] & (Nn - 1);
    return ((const int*)p)[i] & (Nn - 1);
}

// -------- numerically stable log-sigmoid --------
__device__ __forceinline__ float lsig(float x) {
    return fminf(x, 0.0f) - log1pf(expf(-fabsf(x)));
}

// -------- 0) detect index dtype: src starts with arange(N) --------
__global__ void k_detect(const void* __restrict__ ei) {
    // as int64, element 1 == 1; as int32 storage read as int64, it's 1<<32
    long long v = ((const long long*)ei)[1];
    g_is64 = (v == 1LL) ? 1 : 0;
}

// -------- 1) reset all scratch (graph replays must be idempotent) --------
__global__ void k_init() {
    int i = blockIdx.x * blockDim.x + threadIdx.x;
    int stride = gridDim.x * blockDim.x;
    for (int w = i; w < NWORDS; w += stride) g_bitmask[w] = 0u;
    if (i < Nn) { g_deg[i] = 0; g_fill[i] = 0; }
    if (i == 0) { g_nnz = 0; g_pos = 0.0; g_neg = 0.0; }
}

// -------- 2) dedup edges + count degrees --------
__global__ void k_dedup(const void* __restrict__ ei) {
    int i = blockIdx.x * blockDim.x + threadIdx.x;
    if (i >= Ee) return;
    int s = fetch_idx(ei, i);
    int d = fetch_idx(ei, Ee + i);
    int idx = (s << 13) | d;
    uint32_t bit = 1u << (idx & 31);
    uint32_t old = atomicOr(&g_bitmask[idx >> 5], bit);
    if (!(old & bit)) {
        int p = atomicAdd(&g_nnz, 1);
        g_elist[p] = idx;
        atomicAdd(&g_deg[s], 1);
    }
}

// -------- 3) exclusive scan of degrees -> CSR row ptr; fused D^-1/2 --------
__global__ void k_scan() {
    __shared__ int tot[1024];
    int t = threadIdx.x;
    int base = t * 8;
    int local[8];
    int s = 0;
#pragma unroll
    for (int i = 0; i < 8; i++) { local[i] = s; s += g_deg[base + i]; }
    tot[t] = s;
    __syncthreads();
    for (int off = 1; off < 1024; off <<= 1) {
        int v = (t >= off) ? tot[t - off] : 0;
        __syncthreads();
        tot[t] += v;
        __syncthreads();
    }
    int excl = (t == 0) ? 0 : tot[t - 1];
#pragma unroll
    for (int i = 0; i < 8; i++) {
        g_ptr[base + i]  = excl + local[i];
        g_dinv[base + i] = rsqrtf((float)max(g_deg[base + i], 1));
    }
    if (t == 1023) g_ptr[Nn] = tot[1023];
}

// -------- 4) scatter dedup'd edges into CSR --------
__global__ void k_scatter() {
    int i = blockIdx.x * blockDim.x + threadIdx.x;
    if (i >= g_nnz) return;
    int idx = g_elist[i];
    int s = idx >> 13;
    int d = idx & (Nn - 1);
    int p = g_ptr[s] + atomicAdd(&g_fill[s], 1);
    if (p < Ee) g_csr[p] = d;
}

// -------- 5) one diffusion step: out[r] = dinv[r] * sum_j dinv[j]*in[j] --------
// One warp per row; each lane holds 4 channels (float4).
__global__ void k_spmm(const float* __restrict__ ext, int insel, int outsel) {
    const float* __restrict__ in =
        (insel == 0) ? ext : ((insel == 1) ? g_bufA : g_bufB);
    float* __restrict__ out = (outsel == 1) ? g_bufA : g_bufB;

    int warp = (blockIdx.x * blockDim.x + threadIdx.x) >> 5;
    int lane = threadIdx.x & 31;
    if (warp >= Nn) return;

    int start = g_ptr[warp];
    int end   = g_ptr[warp + 1];
    float dr  = g_dinv[warp];

    float4 acc = make_float4(0.f, 0.f, 0.f, 0.f);
#pragma unroll 4
    for (int k = start; k < end; k++) {
        int j   = __ldg(&g_csr[k]);
        float w = dr * __ldg(&g_dinv[j]);
        float4 v = *reinterpret_cast<const float4*>(in + j * Cc + lane * 4);
        acc.x += w * v.x;
        acc.y += w * v.y;
        acc.z += w * v.z;
        acc.w += w * v.w;
    }
    *reinterpret_cast<float4*>(out + warp * Cc + lane * 4) = acc;
}

// -------- 6) positive-pair loss over all E edges (with duplicates!) --------
__global__ void k_pos(const void* __restrict__ ei) {
    const float* __restrict__ emb = g_bufB;   // final embeddings after 10 steps
    int gw   = (blockIdx.x * blockDim.x + threadIdx.x) >> 5;
    int lane = threadIdx.x & 31;
    int nw   = (gridDim.x * blockDim.x) >> 5;

    float local = 0.f;
    for (int e = gw; e < Ee; e += nw) {
        int s = fetch_idx(ei, e);
        int d = fetch_idx(ei, Ee + e);
        float4 a = *reinterpret_cast<const float4*>(emb + s * Cc + lane * 4);
        float4 b = *reinterpret_cast<const float4*>(emb + d * Cc + lane * 4);
        float dot = a.x * b.x + a.y * b.y + a.z * b.z + a.w * b.w;
#pragma unroll
        for (int o = 16; o; o >>= 1) dot += __shfl_xor_sync(0xffffffffu, dot, o);
        if (lane == 0) local += lsig(dot * 2.0f);   // /TEMPERATURE, T = 0.5
    }
    __shared__ float sm[8];
    if (lane == 0) sm[threadIdx.x >> 5] = local;
    __syncthreads();
    if (threadIdx.x == 0) {
        float s = 0.f;
#pragma unroll
        for (int i = 0; i < 8; i++) s += sm[i];
        atomicAdd(&g_pos, (double)s);
    }
}

// -------- 7) negative-pair loss over N rows --------
__global__ void k_neg(const void* __restrict__ ri) {
    const float* __restrict__ emb = g_bufB;
    int gw   = (blockIdx.x * blockDim.x + threadIdx.x) >> 5;
    int lane = threadIdx.x & 31;

    float local = 0.f;
    if (gw < Nn) {
        int j = fetch_idx(ri, gw);
        float4 a = *reinterpret_cast<const float4*>(emb + gw * Cc + lane * 4);
        float4 b = *reinterpret_cast<const float4*>(emb + j * Cc + lane * 4);
        float dot = a.x * b.x + a.y * b.y + a.z * b.z + a.w * b.w;
#pragma unroll
        for (int o = 16; o; o >>= 1) dot += __shfl_xor_sync(0xffffffffu, dot, o);
        if (lane == 0) local = lsig(-dot * 2.0f);
    }
    __shared__ float sm[8];
    if (lane == 0) sm[threadIdx.x >> 5] = local;
    __syncthreads();
    if (threadIdx.x == 0) {
        float s = 0.f;
#pragma unroll
        for (int i = 0; i < 8; i++) s += sm[i];
        atomicAdd(&g_neg, (double)s);
    }
}

// -------- 8) finalize: loss = -mean(ls(pos)) - mean(ls(-neg)) --------
__global__ void k_final(float* __restrict__ out) {
    out[0] = (float)(-(g_pos / (double)Ee) - (g_neg / (double)Nn));
}

extern "C" void kernel_launch(void* const* d_in, const int* in_sizes, int n_in,
                              void* d_out, int out_size) {
    const float* emb = (const float*)d_in[0];   // [N, C] fp32
    const void*  ei  = d_in[1];                 // [2, E] int32 or int64
    const void*  ri  = d_in[2];                 // [N]    int32 or int64
    float* out = (float*)d_out;

    k_detect<<<1, 1>>>(ei);
    k_init<<<2048, 256>>>();
    k_dedup<<<Ee / 256, 256>>>(ei);
    k_scan<<<1, 1024>>>();
    k_scatter<<<Ee / 256, 256>>>();

    // 10 diffusion steps: input -> A -> B -> A -> ... -> B (final in g_bufB)
    k_spmm<<<Nn / 8, 256>>>(emb, 0, 1);
    for (int s = 1; s < 10; s++) {
        int insel  = (s & 1) ? 1 : 2;
        int outsel = (s & 1) ? 2 : 1;
        k_spmm<<<Nn / 8, 256>>>(nullptr, insel, outsel);
    }

    k_pos<<<512, 256>>>(ei);
    k_neg<<<Nn / 8, 256>>>(ri);
    k_final<<<1, 1>>>(out);
}